// round 1
// baseline (speedup 1.0000x reference)
#include <cuda_runtime.h>
#include <cuda_bf16.h>
#include <cstdint>
#include <math.h>

// Problem constants (from reference)
#define NNODES 100000
#define NEDGES 3200000
#define FIN    512
#define FHID   256
#define NCLS   40

// ---------------- device scratch (no allocations allowed) ----------------
__device__ float g_H0[(size_t)NNODES * FHID];   // x @ W1
__device__ float g_H1[(size_t)NNODES * FHID];   // spmm(A, H0)   (atomics)
__device__ float g_P [(size_t)NNODES * NCLS];   // relu(H1+b1) @ W2
__device__ int   g_row[NEDGES];
__device__ int   g_col[NEDGES];
__device__ int   g_is64;

// ---------------- edge index width detection + conversion ----------------
__global__ void detect_kernel(const void* rowp) {
    if (threadIdx.x == 0 && blockIdx.x == 0) {
        const int* p = (const int*)rowp;
        int is64 = 1;
        #pragma unroll 4
        for (int i = 0; i < 128; i++) {
            if (p[2 * i + 1] != 0) { is64 = 0; break; }
        }
        g_is64 = is64;
    }
}

__global__ void convert_kernel(const void* rowp, const void* colp) {
    int i = blockIdx.x * blockDim.x + threadIdx.x;
    if (i >= NEDGES) return;
    if (g_is64) {
        g_row[i] = (int)((const long long*)rowp)[i];
        g_col[i] = (int)((const long long*)colp)[i];
    } else {
        g_row[i] = ((const int*)rowp)[i];
        g_col[i] = ((const int*)colp)[i];
    }
}

// ---------------- zero kernels ----------------
__global__ void zero_H1_kernel() {
    size_t n4 = (size_t)NNODES * FHID / 4;
    float4* p = (float4*)g_H1;
    for (size_t i = blockIdx.x * blockDim.x + threadIdx.x; i < n4;
         i += (size_t)gridDim.x * blockDim.x) {
        p[i] = make_float4(0.f, 0.f, 0.f, 0.f);
    }
}

__global__ void zero_out_kernel(float* out) {
    size_t n4 = (size_t)NNODES * NCLS / 4;
    float4* p = (float4*)out;
    for (size_t i = blockIdx.x * blockDim.x + threadIdx.x; i < n4;
         i += (size_t)gridDim.x * blockDim.x) {
        p[i] = make_float4(0.f, 0.f, 0.f, 0.f);
    }
}

// ---------------- GEMM1: g_H0 = x @ W1  (M=100000, K=512, N=256) --------
// 128x128 block tile, BK=16, 256 threads, 8x8 per thread.
__global__ __launch_bounds__(256) void gemm1_kernel(
    const float* __restrict__ A,   // [M, 512]
    const float* __restrict__ B)   // [512, 256]
{
    __shared__ float As[16][128];
    __shared__ float Bs[16][128];

    const int tid = threadIdx.x;
    const int bm  = blockIdx.y * 128;
    const int bn  = blockIdx.x * 128;
    const int tx  = tid % 16;
    const int ty  = tid / 16;

    const int aRow = tid / 4;          // 0..63
    const int aCol = (tid % 4) * 4;    // 0,4,8,12
    const int bRow = tid / 32;         // 0..7
    const int bCol = (tid % 32) * 4;   // 0..124

    float acc[8][8];
    #pragma unroll
    for (int i = 0; i < 8; i++)
        #pragma unroll
        for (int j = 0; j < 8; j++) acc[i][j] = 0.f;

    for (int k0 = 0; k0 < FIN; k0 += 16) {
        #pragma unroll
        for (int r = 0; r < 2; r++) {
            int row = bm + aRow + r * 64;
            float4 v = make_float4(0.f, 0.f, 0.f, 0.f);
            if (row < NNODES)
                v = *(const float4*)(A + (size_t)row * FIN + k0 + aCol);
            As[aCol + 0][aRow + r * 64] = v.x;
            As[aCol + 1][aRow + r * 64] = v.y;
            As[aCol + 2][aRow + r * 64] = v.z;
            As[aCol + 3][aRow + r * 64] = v.w;
        }
        #pragma unroll
        for (int r = 0; r < 2; r++) {
            int krow = k0 + bRow + r * 8;
            *(float4*)(&Bs[bRow + r * 8][bCol]) =
                *(const float4*)(B + (size_t)krow * FHID + bn + bCol);
        }
        __syncthreads();

        #pragma unroll
        for (int k = 0; k < 16; k++) {
            float a[8], b[8];
            *(float4*)&a[0] = *(float4*)&As[k][ty * 8];
            *(float4*)&a[4] = *(float4*)&As[k][ty * 8 + 4];
            *(float4*)&b[0] = *(float4*)&Bs[k][tx * 8];
            *(float4*)&b[4] = *(float4*)&Bs[k][tx * 8 + 4];
            #pragma unroll
            for (int i = 0; i < 8; i++)
                #pragma unroll
                for (int j = 0; j < 8; j++)
                    acc[i][j] = fmaf(a[i], b[j], acc[i][j]);
        }
        __syncthreads();
    }

    #pragma unroll
    for (int i = 0; i < 8; i++) {
        int row = bm + ty * 8 + i;
        if (row < NNODES) {
            float* c = g_H0 + (size_t)row * FHID + bn + tx * 8;
            *(float4*)(c)     = *(float4*)&acc[i][0];
            *(float4*)(c + 4) = *(float4*)&acc[i][4];
        }
    }
}

// ---------------- SpMM1: g_H1[r] += val * g_H0[c], 256 feats -------------
// One warp per edge: 64 float4 gathers + 64 vector reds per warp (2/lane).
__global__ __launch_bounds__(256) void spmm1_kernel(const float* __restrict__ val) {
    int e = blockIdx.x * 8 + (threadIdx.x >> 5);
    if (e >= NEDGES) return;
    int lane = threadIdx.x & 31;
    int r = g_row[e];
    int c = g_col[e];
    float v = val[e];
    const float4* src = (const float4*)(g_H0 + (size_t)c * FHID);
    float* dst = g_H1 + (size_t)r * FHID;
    #pragma unroll
    for (int j = 0; j < 2; j++) {
        int idx = lane + 32 * j;
        float4 t = src[idx];
        float x0 = t.x * v, x1 = t.y * v, x2 = t.z * v, x3 = t.w * v;
        asm volatile("red.global.add.v4.f32 [%0], {%1,%2,%3,%4};"
                     :: "l"(dst + idx * 4), "f"(x0), "f"(x1), "f"(x2), "f"(x3)
                     : "memory");
    }
}

// ---------------- GEMM2: g_P = relu(g_H1 + b1) @ W2  (K=256, N=40) -------
// 256 threads, 64 rows/block, 4 threads per row, 10 output cols per thread.
__global__ __launch_bounds__(256) void gemm2_kernel(
    const float* __restrict__ b1,
    const float* __restrict__ W2)   // [256, 40]
{
    __shared__ float shW[FHID * NCLS];   // 40 KB
    __shared__ float shb[FHID];          // 1 KB

    const int tid = threadIdx.x;
    for (int i = tid; i < FHID * NCLS; i += 256) shW[i] = W2[i];
    for (int i = tid; i < FHID; i += 256) shb[i] = b1[i];
    __syncthreads();

    const int row = blockIdx.x * 64 + tid / 4;
    if (row >= NNODES) return;
    const int c0 = (tid % 4) * 10;

    const float* h = g_H1 + (size_t)row * FHID;
    float acc[10];
    #pragma unroll
    for (int j = 0; j < 10; j++) acc[j] = 0.f;

    #pragma unroll 4
    for (int k = 0; k < FHID; k++) {
        float hv = fmaxf(h[k] + shb[k], 0.f);
        const float* w = &shW[k * NCLS + c0];
        #pragma unroll
        for (int j = 0; j < 5; j++) {
            float2 wv = *(const float2*)(w + 2 * j);
            acc[2 * j + 0] = fmaf(hv, wv.x, acc[2 * j + 0]);
            acc[2 * j + 1] = fmaf(hv, wv.y, acc[2 * j + 1]);
        }
    }
    float* p = g_P + (size_t)row * NCLS + c0;
    #pragma unroll
    for (int j = 0; j < 5; j++)
        *(float2*)(p + 2 * j) = make_float2(acc[2 * j], acc[2 * j + 1]);
}

// ---------------- SpMM2: out[r] += val * g_P[c], 40 feats ---------------
// 320 threads/block = 32 edges/block, 10 float4-chunks per edge.
__global__ __launch_bounds__(320) void spmm2_kernel(const float* __restrict__ val,
                                                    float* __restrict__ out) {
    int t = threadIdx.x;
    int le = t / 10;
    int ch = t - le * 10;
    int e = blockIdx.x * 32 + le;
    if (le >= 32 || e >= NEDGES) return;
    int r = g_row[e];
    int c = g_col[e];
    float v = val[e];
    float4 p = *(const float4*)(g_P + (size_t)c * NCLS + ch * 4);
    float x0 = p.x * v, x1 = p.y * v, x2 = p.z * v, x3 = p.w * v;
    asm volatile("red.global.add.v4.f32 [%0], {%1,%2,%3,%4};"
                 :: "l"(out + (size_t)r * NCLS + ch * 4),
                    "f"(x0), "f"(x1), "f"(x2), "f"(x3)
                 : "memory");
}

// ---------------- bias + log_softmax (in place), warp per row -----------
__global__ __launch_bounds__(256) void softmax_kernel(float* __restrict__ out,
                                                      const float* __restrict__ b2) {
    int row = (blockIdx.x * 256 + threadIdx.x) >> 5;
    if (row >= NNODES) return;
    int lane = threadIdx.x & 31;
    float* p = out + (size_t)row * NCLS;

    float v0 = p[lane] + b2[lane];
    float v1 = (lane < 8) ? (p[32 + lane] + b2[32 + lane]) : -INFINITY;

    float m = fmaxf(v0, v1);
    #pragma unroll
    for (int off = 16; off > 0; off >>= 1)
        m = fmaxf(m, __shfl_xor_sync(0xFFFFFFFFu, m, off));

    float s = expf(v0 - m) + ((lane < 8) ? expf(v1 - m) : 0.f);
    #pragma unroll
    for (int off = 16; off > 0; off >>= 1)
        s += __shfl_xor_sync(0xFFFFFFFFu, s, off);

    float ls = m + logf(s);
    p[lane] = v0 - ls;
    if (lane < 8) p[32 + lane] = v1 - ls;
}

// ---------------- launch ----------------
extern "C" void kernel_launch(void* const* d_in, const int* in_sizes, int n_in,
                              void* d_out, int out_size) {
    const float* x    = (const float*)d_in[0];
    const void*  erow = d_in[1];
    const void*  ecol = d_in[2];
    const float* eval = (const float*)d_in[3];
    const float* W1   = (const float*)d_in[4];
    const float* b1   = (const float*)d_in[5];
    const float* W2   = (const float*)d_in[6];
    const float* b2   = (const float*)d_in[7];
    float* out = (float*)d_out;

    detect_kernel<<<1, 32>>>(erow);
    convert_kernel<<<(NEDGES + 255) / 256, 256>>>(erow, ecol);
    zero_H1_kernel<<<2048, 256>>>();
    {
        dim3 grid(FHID / 128, (NNODES + 127) / 128);  // (2, 782)
        gemm1_kernel<<<grid, 256>>>(x, W1);
    }
    spmm1_kernel<<<NEDGES / 8, 256>>>(eval);
    zero_out_kernel<<<1024, 256>>>(out);
    gemm2_kernel<<<(NNODES + 63) / 64, 256>>>(b1, W2);
    spmm2_kernel<<<NEDGES / 32, 320>>>(eval, out);
    softmax_kernel<<<(NNODES * 32 + 255) / 256, 256>>>(out, b2);
}

// round 2
// speedup vs baseline: 1.6845x; 1.6845x over previous
#include <cuda_runtime.h>
#include <cuda_bf16.h>
#include <cstdint>
#include <math.h>

#define NNODES 100000
#define NEDGES 3200000
#define FIN    512
#define FHID   256
#define NCLS   40

// ---------------- device scratch ----------------
__device__ float g_H0[(size_t)NNODES * FHID];   // x @ W1
__device__ float g_H [(size_t)NNODES * FHID];   // relu(spmm(A,H0) + b1)
__device__ float g_P [(size_t)NNODES * NCLS];   // g_H @ W2
__device__ int   g_deg[NNODES];
__device__ int   g_rowptr[NNODES + 1];
__device__ int   g_fill[NNODES];
__device__ int   g_bsum[128];
__device__ int   g_boff[128];
__device__ int   g_ccol[NEDGES];
__device__ float g_cval[NEDGES];
__device__ int   g_is64;

// ---------------- edge index width detection ----------------
__global__ void detect_kernel(const void* rowp) {
    if (threadIdx.x == 0 && blockIdx.x == 0) {
        const int* p = (const int*)rowp;
        int is64 = 1;
        for (int i = 0; i < 128; i++) {
            if (p[2 * i + 1] != 0) { is64 = 0; break; }
        }
        g_is64 = is64;
    }
}

__device__ __forceinline__ int load_idx(const void* p, int i, int is64) {
    return is64 ? (int)((const long long*)p)[i] : ((const int*)p)[i];
}

// ---------------- CSR build ----------------
__global__ void zero_deg_kernel() {
    int i = blockIdx.x * 1024 + threadIdx.x;
    if (i < NNODES) g_deg[i] = 0;
}

__global__ __launch_bounds__(256) void hist_kernel(const void* rowp) {
    int i = blockIdx.x * 256 + threadIdx.x;
    if (i >= NEDGES) return;
    int r = load_idx(rowp, i, g_is64);
    atomicAdd(&g_deg[r], 1);
}

// k1: per-1024-chunk sums
__global__ __launch_bounds__(1024) void scan_k1_kernel() {
    __shared__ int sh[1024];
    int t = threadIdx.x;
    int i = blockIdx.x * 1024 + t;
    sh[t] = (i < NNODES) ? g_deg[i] : 0;
    __syncthreads();
    for (int off = 512; off > 0; off >>= 1) {
        if (t < off) sh[t] += sh[t + off];
        __syncthreads();
    }
    if (t == 0) g_bsum[blockIdx.x] = sh[0];
}

// k2: scan the 98 block sums
__global__ void scan_k2_kernel(int nblocks) {
    __shared__ int sh[128];
    int t = threadIdx.x;
    int x = (t < nblocks) ? g_bsum[t] : 0;
    sh[t] = x;
    __syncthreads();
    for (int off = 1; off < 128; off <<= 1) {
        int v = (t >= off) ? sh[t - off] : 0;
        __syncthreads();
        sh[t] += v;
        __syncthreads();
    }
    if (t < nblocks) g_boff[t] = sh[t] - x;   // exclusive
    if (t == 0) g_rowptr[NNODES] = NEDGES;
}

// k3: per-chunk exclusive scan + offset
__global__ __launch_bounds__(1024) void scan_k3_kernel() {
    __shared__ int sh[1024];
    int t = threadIdx.x;
    int i = blockIdx.x * 1024 + t;
    int x = (i < NNODES) ? g_deg[i] : 0;
    sh[t] = x;
    __syncthreads();
    for (int off = 1; off < 1024; off <<= 1) {
        int v = (t >= off) ? sh[t - off] : 0;
        __syncthreads();
        sh[t] += v;
        __syncthreads();
    }
    if (i < NNODES) {
        int excl = sh[t] - x + g_boff[blockIdx.x];
        g_rowptr[i] = excl;
        g_fill[i]   = excl;
    }
}

__global__ __launch_bounds__(256) void scatter_kernel(const void* rowp, const void* colp,
                                                      const float* __restrict__ val) {
    int i = blockIdx.x * 256 + threadIdx.x;
    if (i >= NEDGES) return;
    int is64 = g_is64;
    int r = load_idx(rowp, i, is64);
    int c = load_idx(colp, i, is64);
    int pos = atomicAdd(&g_fill[r], 1);
    g_ccol[pos] = c;
    g_cval[pos] = val[i];
}

// ---------------- GEMM1: g_H0 = x @ W1  (M=100000, K=512, N=256) --------
__global__ __launch_bounds__(256) void gemm1_kernel(
    const float* __restrict__ A, const float* __restrict__ B)
{
    __shared__ float As[16][128];
    __shared__ float Bs[16][128];

    const int tid = threadIdx.x;
    const int bm  = blockIdx.y * 128;
    const int bn  = blockIdx.x * 128;
    const int tx  = tid % 16;
    const int ty  = tid / 16;

    const int aRow = tid / 4;
    const int aCol = (tid % 4) * 4;
    const int bRow = tid / 32;
    const int bCol = (tid % 32) * 4;

    float acc[8][8];
    #pragma unroll
    for (int i = 0; i < 8; i++)
        #pragma unroll
        for (int j = 0; j < 8; j++) acc[i][j] = 0.f;

    for (int k0 = 0; k0 < FIN; k0 += 16) {
        #pragma unroll
        for (int r = 0; r < 2; r++) {
            int row = bm + aRow + r * 64;
            float4 v = make_float4(0.f, 0.f, 0.f, 0.f);
            if (row < NNODES)
                v = *(const float4*)(A + (size_t)row * FIN + k0 + aCol);
            As[aCol + 0][aRow + r * 64] = v.x;
            As[aCol + 1][aRow + r * 64] = v.y;
            As[aCol + 2][aRow + r * 64] = v.z;
            As[aCol + 3][aRow + r * 64] = v.w;
        }
        #pragma unroll
        for (int r = 0; r < 2; r++) {
            int krow = k0 + bRow + r * 8;
            *(float4*)(&Bs[bRow + r * 8][bCol]) =
                *(const float4*)(B + (size_t)krow * FHID + bn + bCol);
        }
        __syncthreads();

        #pragma unroll
        for (int k = 0; k < 16; k++) {
            float a[8], b[8];
            *(float4*)&a[0] = *(float4*)&As[k][ty * 8];
            *(float4*)&a[4] = *(float4*)&As[k][ty * 8 + 4];
            *(float4*)&b[0] = *(float4*)&Bs[k][tx * 8];
            *(float4*)&b[4] = *(float4*)&Bs[k][tx * 8 + 4];
            #pragma unroll
            for (int i = 0; i < 8; i++)
                #pragma unroll
                for (int j = 0; j < 8; j++)
                    acc[i][j] = fmaf(a[i], b[j], acc[i][j]);
        }
        __syncthreads();
    }

    #pragma unroll
    for (int i = 0; i < 8; i++) {
        int row = bm + ty * 8 + i;
        if (row < NNODES) {
            float* c = g_H0 + (size_t)row * FHID + bn + tx * 8;
            *(float4*)(c)     = *(float4*)&acc[i][0];
            *(float4*)(c + 4) = *(float4*)&acc[i][4];
        }
    }
}

// ---------------- SpMM1 (CSR, warp/row) + bias + relu -------------------
// lane owns feats [lane*4, lane*4+4) and [128+lane*4, ...+4)
__global__ __launch_bounds__(256) void spmm1_csr_kernel(const float* __restrict__ b1) {
    int row  = blockIdx.x * 8 + (threadIdx.x >> 5);
    int lane = threadIdx.x & 31;
    int start = g_rowptr[row];
    int end   = g_rowptr[row + 1];

    float4 a0 = make_float4(0.f, 0.f, 0.f, 0.f);
    float4 a1 = make_float4(0.f, 0.f, 0.f, 0.f);

    for (int e0 = start; e0 < end; e0 += 32) {
        int m = min(32, end - e0);
        int   c = 0;
        float v = 0.f;
        if (lane < m) { c = g_ccol[e0 + lane]; v = g_cval[e0 + lane]; }
        for (int j = 0; j < m; j++) {
            int   cj = __shfl_sync(0xFFFFFFFFu, c, j);
            float vj = __shfl_sync(0xFFFFFFFFu, v, j);
            const float4* s = (const float4*)(g_H0 + (size_t)cj * FHID);
            float4 f0 = s[lane];
            float4 f1 = s[lane + 32];
            a0.x = fmaf(vj, f0.x, a0.x); a0.y = fmaf(vj, f0.y, a0.y);
            a0.z = fmaf(vj, f0.z, a0.z); a0.w = fmaf(vj, f0.w, a0.w);
            a1.x = fmaf(vj, f1.x, a1.x); a1.y = fmaf(vj, f1.y, a1.y);
            a1.z = fmaf(vj, f1.z, a1.z); a1.w = fmaf(vj, f1.w, a1.w);
        }
    }

    const float4* bb = (const float4*)b1;
    float4 t0 = bb[lane], t1 = bb[lane + 32];
    a0.x = fmaxf(a0.x + t0.x, 0.f); a0.y = fmaxf(a0.y + t0.y, 0.f);
    a0.z = fmaxf(a0.z + t0.z, 0.f); a0.w = fmaxf(a0.w + t0.w, 0.f);
    a1.x = fmaxf(a1.x + t1.x, 0.f); a1.y = fmaxf(a1.y + t1.y, 0.f);
    a1.z = fmaxf(a1.z + t1.z, 0.f); a1.w = fmaxf(a1.w + t1.w, 0.f);

    float4* d = (float4*)(g_H + (size_t)row * FHID);
    d[lane]      = a0;
    d[lane + 32] = a1;
}

// ---------------- GEMM2: g_P = g_H @ W2  (K=256, N=40) ------------------
// block = 256 threads, 64 rows; thread: 2 rows x 5 cols; W2^T in smem.
#define W2STRIDE 260
__global__ __launch_bounds__(256) void gemm2_kernel(const float* __restrict__ W2) {
    __shared__ float shWT[NCLS * W2STRIDE];   // shWT[c][k], 41.6 KB

    const int tid = threadIdx.x;
    for (int idx = tid; idx < FHID * NCLS; idx += 256) {
        int k = idx / NCLS, c = idx % NCLS;
        shWT[c * W2STRIDE + k] = W2[idx];
    }
    __syncthreads();

    const int rp = tid >> 3;            // 0..31
    const int c0 = (tid & 7) * 5;       // 0..35
    int r0 = blockIdx.x * 64 + rp * 2;
    int r1 = r0 + 1;
    bool v0 = r0 < NNODES, v1 = r1 < NNODES;
    int r0c = v0 ? r0 : NNODES - 1;
    int r1c = v1 ? r1 : NNODES - 1;

    const float4* h0 = (const float4*)(g_H + (size_t)r0c * FHID);
    const float4* h1 = (const float4*)(g_H + (size_t)r1c * FHID);

    float acc0[5] = {0.f, 0.f, 0.f, 0.f, 0.f};
    float acc1[5] = {0.f, 0.f, 0.f, 0.f, 0.f};

    #pragma unroll 4
    for (int kq = 0; kq < FHID / 4; kq++) {
        float4 ha = h0[kq];
        float4 hb = h1[kq];
        #pragma unroll
        for (int j = 0; j < 5; j++) {
            float4 w = *(const float4*)&shWT[(c0 + j) * W2STRIDE + kq * 4];
            acc0[j] = fmaf(ha.x, w.x, acc0[j]); acc0[j] = fmaf(ha.y, w.y, acc0[j]);
            acc0[j] = fmaf(ha.z, w.z, acc0[j]); acc0[j] = fmaf(ha.w, w.w, acc0[j]);
            acc1[j] = fmaf(hb.x, w.x, acc1[j]); acc1[j] = fmaf(hb.y, w.y, acc1[j]);
            acc1[j] = fmaf(hb.z, w.z, acc1[j]); acc1[j] = fmaf(hb.w, w.w, acc1[j]);
        }
    }

    if (v0) {
        float* p = g_P + (size_t)r0 * NCLS + c0;
        #pragma unroll
        for (int j = 0; j < 5; j++) p[j] = acc0[j];
    }
    if (v1) {
        float* p = g_P + (size_t)r1 * NCLS + c0;
        #pragma unroll
        for (int j = 0; j < 5; j++) p[j] = acc1[j];
    }
}

// ---------------- SpMM2 (CSR, warp/row) + bias + log_softmax ------------
__global__ __launch_bounds__(256) void spmm2_csr_kernel(const float* __restrict__ b2,
                                                        float* __restrict__ out) {
    int row  = blockIdx.x * 8 + (threadIdx.x >> 5);
    int lane = threadIdx.x & 31;
    int start = g_rowptr[row];
    int end   = g_rowptr[row + 1];

    float acc0 = 0.f, acc1 = 0.f;

    for (int e0 = start; e0 < end; e0 += 32) {
        int m = min(32, end - e0);
        int   c = 0;
        float v = 0.f;
        if (lane < m) { c = g_ccol[e0 + lane]; v = g_cval[e0 + lane]; }
        for (int j = 0; j < m; j++) {
            int   cj = __shfl_sync(0xFFFFFFFFu, c, j);
            float vj = __shfl_sync(0xFFFFFFFFu, v, j);
            const float* p = g_P + (size_t)cj * NCLS;
            float p0 = p[lane];
            float p1 = (lane < 8) ? p[32 + lane] : 0.f;
            acc0 = fmaf(vj, p0, acc0);
            acc1 = fmaf(vj, p1, acc1);
        }
    }

    float v0 = acc0 + b2[lane];
    float v1 = (lane < 8) ? (acc1 + b2[32 + lane]) : -INFINITY;

    float mx = fmaxf(v0, v1);
    #pragma unroll
    for (int off = 16; off > 0; off >>= 1)
        mx = fmaxf(mx, __shfl_xor_sync(0xFFFFFFFFu, mx, off));

    float s = expf(v0 - mx) + ((lane < 8) ? expf(v1 - mx) : 0.f);
    #pragma unroll
    for (int off = 16; off > 0; off >>= 1)
        s += __shfl_xor_sync(0xFFFFFFFFu, s, off);

    float ls = mx + logf(s);
    float* o = out + (size_t)row * NCLS;
    o[lane] = v0 - ls;
    if (lane < 8) o[32 + lane] = v1 - ls;
}

// ---------------- launch ----------------
extern "C" void kernel_launch(void* const* d_in, const int* in_sizes, int n_in,
                              void* d_out, int out_size) {
    const float* x    = (const float*)d_in[0];
    const void*  erow = d_in[1];
    const void*  ecol = d_in[2];
    const float* eval = (const float*)d_in[3];
    const float* W1   = (const float*)d_in[4];
    const float* b1   = (const float*)d_in[5];
    const float* W2   = (const float*)d_in[6];
    const float* b2   = (const float*)d_in[7];
    float* out = (float*)d_out;

    const int nchunks = (NNODES + 1023) / 1024;   // 98

    detect_kernel<<<1, 32>>>(erow);
    zero_deg_kernel<<<nchunks, 1024>>>();
    hist_kernel<<<NEDGES / 256, 256>>>(erow);
    scan_k1_kernel<<<nchunks, 1024>>>();
    scan_k2_kernel<<<1, 128>>>(nchunks);
    scan_k3_kernel<<<nchunks, 1024>>>();
    scatter_kernel<<<NEDGES / 256, 256>>>(erow, ecol, eval);

    {
        dim3 grid(FHID / 128, (NNODES + 127) / 128);
        gemm1_kernel<<<grid, 256>>>(x, W1);
    }
    spmm1_csr_kernel<<<NNODES / 8, 256>>>(b1);
    gemm2_kernel<<<(NNODES + 63) / 64, 256>>>(W2);
    spmm2_csr_kernel<<<NNODES / 8, 256>>>(b2, out);
}

// round 3
// speedup vs baseline: 1.9904x; 1.1817x over previous
#include <cuda_runtime.h>
#include <cuda_bf16.h>
#include <cstdint>
#include <math.h>

#define NNODES 100000
#define NEDGES 3200000
#define FIN    512
#define FHID   256
#define NCLS   40

// ---------------- device scratch ----------------
__device__ float g_H0[(size_t)NNODES * FHID];   // x @ W1
__device__ float g_H [(size_t)NNODES * FHID];   // relu(spmm(A,H0) + b1)
__device__ float g_P [(size_t)NNODES * NCLS];   // g_H @ W2
__device__ int   g_deg[NNODES];
__device__ int   g_rowptr[NNODES + 1];
__device__ int   g_fill[NNODES];
__device__ int   g_bsum[128];
__device__ int   g_boff[128];
__device__ int   g_ccol[NEDGES];
__device__ float g_cval[NEDGES];
__device__ int   g_is64;

// ---------------- edge index width detection ----------------
__global__ void detect_kernel(const void* rowp) {
    if (threadIdx.x == 0 && blockIdx.x == 0) {
        const int* p = (const int*)rowp;
        int is64 = 1;
        for (int i = 0; i < 128; i++) {
            if (p[2 * i + 1] != 0) { is64 = 0; break; }
        }
        g_is64 = is64;
    }
}

__device__ __forceinline__ int load_idx(const void* p, int i, int is64) {
    return is64 ? (int)((const long long*)p)[i] : ((const int*)p)[i];
}

// ---------------- CSR build ----------------
__global__ void zero_deg_kernel() {
    int i = blockIdx.x * 1024 + threadIdx.x;
    if (i < NNODES) g_deg[i] = 0;
}

__global__ __launch_bounds__(256) void hist_kernel(const void* rowp) {
    int i = blockIdx.x * 256 + threadIdx.x;
    if (i >= NEDGES) return;
    int r = load_idx(rowp, i, g_is64);
    atomicAdd(&g_deg[r], 1);
}

__global__ __launch_bounds__(1024) void scan_k1_kernel() {
    __shared__ int sh[1024];
    int t = threadIdx.x;
    int i = blockIdx.x * 1024 + t;
    sh[t] = (i < NNODES) ? g_deg[i] : 0;
    __syncthreads();
    for (int off = 512; off > 0; off >>= 1) {
        if (t < off) sh[t] += sh[t + off];
        __syncthreads();
    }
    if (t == 0) g_bsum[blockIdx.x] = sh[0];
}

__global__ void scan_k2_kernel(int nblocks) {
    __shared__ int sh[128];
    int t = threadIdx.x;
    int x = (t < nblocks) ? g_bsum[t] : 0;
    sh[t] = x;
    __syncthreads();
    for (int off = 1; off < 128; off <<= 1) {
        int v = (t >= off) ? sh[t - off] : 0;
        __syncthreads();
        sh[t] += v;
        __syncthreads();
    }
    if (t < nblocks) g_boff[t] = sh[t] - x;
    if (t == 0) g_rowptr[NNODES] = NEDGES;
}

__global__ __launch_bounds__(1024) void scan_k3_kernel() {
    __shared__ int sh[1024];
    int t = threadIdx.x;
    int i = blockIdx.x * 1024 + t;
    int x = (i < NNODES) ? g_deg[i] : 0;
    sh[t] = x;
    __syncthreads();
    for (int off = 1; off < 1024; off <<= 1) {
        int v = (t >= off) ? sh[t - off] : 0;
        __syncthreads();
        sh[t] += v;
        __syncthreads();
    }
    if (i < NNODES) {
        int excl = sh[t] - x + g_boff[blockIdx.x];
        g_rowptr[i] = excl;
        g_fill[i]   = excl;
    }
}

__global__ __launch_bounds__(256) void scatter_kernel(const void* rowp, const void* colp,
                                                      const float* __restrict__ val) {
    int i = blockIdx.x * 256 + threadIdx.x;
    if (i >= NEDGES) return;
    int is64 = g_is64;
    int r = load_idx(rowp, i, is64);
    int c = load_idx(colp, i, is64);
    int pos = atomicAdd(&g_fill[r], 1);
    g_ccol[pos] = c;
    g_cval[pos] = val[i];
}

// ---------------- GEMM1 (tensor cores, 3xTF32 split) --------------------
// g_H0 = x @ W1, M=100000, K=512, N=256. Block 128x128, BK=16, 8 warps.
__device__ __forceinline__ uint32_t f2tf(float x) {
    uint32_t u; asm("cvt.rna.tf32.f32 %0, %1;" : "=r"(u) : "f"(x)); return u;
}

__device__ __forceinline__ void mma_tf32(float* d, const uint32_t* a, const uint32_t* b) {
    asm volatile(
      "mma.sync.aligned.m16n8k8.row.col.f32.tf32.tf32.f32 "
      "{%0,%1,%2,%3}, {%4,%5,%6,%7}, {%8,%9}, {%0,%1,%2,%3};\n"
      : "+f"(d[0]), "+f"(d[1]), "+f"(d[2]), "+f"(d[3])
      : "r"(a[0]), "r"(a[1]), "r"(a[2]), "r"(a[3]), "r"(b[0]), "r"(b[1]));
}

#define APAD 20
#define BPAD 136

__global__ __launch_bounds__(256) void gemm1_tc_kernel(
    const float* __restrict__ A,   // [M, 512]
    const float* __restrict__ B)   // [512, 256]
{
    __shared__ float As[2][128][APAD];
    __shared__ float Bs[2][16][BPAD];

    const int tid  = threadIdx.x;
    const int lane = tid & 31;
    const int wid  = tid >> 5;
    const int wm   = wid & 3;       // 0..3  (M)
    const int wn   = wid >> 2;      // 0..1  (N)
    const int bm   = blockIdx.y * 128;
    const int bn   = blockIdx.x * 128;

    const int g  = lane >> 2;       // 0..7
    const int tg = lane & 3;        // 0..3

    // gmem load mapping
    const int aRow = tid >> 2;             // wait: 512 float4 / 256 threads = 2 each
    // A: float4 f in [0,512): row=f>>2, c4=f&3
    // B: float4 f in [0,512): krow=f>>5, c4=f&31

    float acc[2][8][4];
    #pragma unroll
    for (int i = 0; i < 2; i++)
        #pragma unroll
        for (int j = 0; j < 8; j++)
            #pragma unroll
            for (int q = 0; q < 4; q++) acc[i][j][q] = 0.f;

    float4 aReg[2], bReg[2];

    // prologue: load tile 0
    #pragma unroll
    for (int i = 0; i < 2; i++) {
        int f = tid + i * 256;
        int row = f >> 2, c4 = f & 3;
        float4 v = make_float4(0.f, 0.f, 0.f, 0.f);
        if (bm + row < NNODES)
            v = *(const float4*)(A + (size_t)(bm + row) * FIN + c4 * 4);
        As[0][row][c4 * 4 + 0] = v.x;
        As[0][row][c4 * 4 + 1] = v.y;
        As[0][row][c4 * 4 + 2] = v.z;
        As[0][row][c4 * 4 + 3] = v.w;
    }
    #pragma unroll
    for (int i = 0; i < 2; i++) {
        int f = tid + i * 256;
        int krow = f >> 5, c4 = f & 31;
        float4 v = *(const float4*)(B + (size_t)krow * FHID + bn + c4 * 4);
        Bs[0][krow][c4 * 4 + 0] = v.x;
        Bs[0][krow][c4 * 4 + 1] = v.y;
        Bs[0][krow][c4 * 4 + 2] = v.z;
        Bs[0][krow][c4 * 4 + 3] = v.w;
    }
    __syncthreads();

    const int NITER = FIN / 16;   // 32
    for (int it = 0; it < NITER; it++) {
        int s = it & 1;
        // prefetch next tile into regs
        if (it + 1 < NITER) {
            int k0 = (it + 1) * 16;
            #pragma unroll
            for (int i = 0; i < 2; i++) {
                int f = tid + i * 256;
                int row = f >> 2, c4 = f & 3;
                aReg[i] = make_float4(0.f, 0.f, 0.f, 0.f);
                if (bm + row < NNODES)
                    aReg[i] = *(const float4*)(A + (size_t)(bm + row) * FIN + k0 + c4 * 4);
                int krow = f >> 5, c4b = f & 31;
                bReg[i] = *(const float4*)(B + (size_t)(k0 + krow) * FHID + bn + c4b * 4);
            }
        }

        // compute: 2 k8 chunks
        #pragma unroll
        for (int c = 0; c < 2; c++) {
            // A fragments (hi/lo) for both m-tiles
            uint32_t ah[2][4], al[2][4];
            #pragma unroll
            for (int mt = 0; mt < 2; mt++) {
                int r0 = wm * 32 + mt * 16 + g;
                int k  = c * 8 + tg;
                float a0 = As[s][r0][k];
                float a1 = As[s][r0 + 8][k];
                float a2 = As[s][r0][k + 4];
                float a3 = As[s][r0 + 8][k + 4];
                ah[mt][0] = f2tf(a0); al[mt][0] = f2tf(a0 - __uint_as_float(ah[mt][0]));
                ah[mt][1] = f2tf(a1); al[mt][1] = f2tf(a1 - __uint_as_float(ah[mt][1]));
                ah[mt][2] = f2tf(a2); al[mt][2] = f2tf(a2 - __uint_as_float(ah[mt][2]));
                ah[mt][3] = f2tf(a3); al[mt][3] = f2tf(a3 - __uint_as_float(ah[mt][3]));
            }
            #pragma unroll
            for (int nt = 0; nt < 8; nt++) {
                int n = wn * 64 + nt * 8 + g;
                int k = c * 8 + tg;
                float b0 = Bs[s][k][n];
                float b1 = Bs[s][k + 4][n];
                uint32_t bh[2], bl[2];
                bh[0] = f2tf(b0); bl[0] = f2tf(b0 - __uint_as_float(bh[0]));
                bh[1] = f2tf(b1); bl[1] = f2tf(b1 - __uint_as_float(bh[1]));
                #pragma unroll
                for (int mt = 0; mt < 2; mt++) {
                    mma_tf32(acc[mt][nt], ah[mt], bl);
                    mma_tf32(acc[mt][nt], al[mt], bh);
                    mma_tf32(acc[mt][nt], ah[mt], bh);
                }
            }
        }

        // store next tile
        if (it + 1 < NITER) {
            int ns = (it + 1) & 1;
            #pragma unroll
            for (int i = 0; i < 2; i++) {
                int f = tid + i * 256;
                int row = f >> 2, c4 = f & 3;
                As[ns][row][c4 * 4 + 0] = aReg[i].x;
                As[ns][row][c4 * 4 + 1] = aReg[i].y;
                As[ns][row][c4 * 4 + 2] = aReg[i].z;
                As[ns][row][c4 * 4 + 3] = aReg[i].w;
                int krow = f >> 5, c4b = f & 31;
                Bs[ns][krow][c4b * 4 + 0] = bReg[i].x;
                Bs[ns][krow][c4b * 4 + 1] = bReg[i].y;
                Bs[ns][krow][c4b * 4 + 2] = bReg[i].z;
                Bs[ns][krow][c4b * 4 + 3] = bReg[i].w;
            }
            __syncthreads();
        }
    }

    // epilogue
    #pragma unroll
    for (int mt = 0; mt < 2; mt++) {
        int r0 = bm + wm * 32 + mt * 16 + g;
        #pragma unroll
        for (int nt = 0; nt < 8; nt++) {
            int cc = bn + wn * 64 + nt * 8 + 2 * tg;
            if (r0 < NNODES)
                *(float2*)(g_H0 + (size_t)r0 * FHID + cc) =
                    make_float2(acc[mt][nt][0], acc[mt][nt][1]);
            if (r0 + 8 < NNODES)
                *(float2*)(g_H0 + (size_t)(r0 + 8) * FHID + cc) =
                    make_float2(acc[mt][nt][2], acc[mt][nt][3]);
        }
    }
}

// ---------------- SpMM1 (CSR, warp/row) + bias + relu -------------------
__global__ __launch_bounds__(256) void spmm1_csr_kernel(const float* __restrict__ b1) {
    int row  = blockIdx.x * 8 + (threadIdx.x >> 5);
    int lane = threadIdx.x & 31;
    int start = g_rowptr[row];
    int end   = g_rowptr[row + 1];

    float4 a0 = make_float4(0.f, 0.f, 0.f, 0.f);
    float4 a1 = make_float4(0.f, 0.f, 0.f, 0.f);

    for (int e0 = start; e0 < end; e0 += 32) {
        int m = min(32, end - e0);
        int   c = 0;
        float v = 0.f;
        if (lane < m) { c = g_ccol[e0 + lane]; v = g_cval[e0 + lane]; }
        for (int j = 0; j < m; j++) {
            int   cj = __shfl_sync(0xFFFFFFFFu, c, j);
            float vj = __shfl_sync(0xFFFFFFFFu, v, j);
            const float4* s = (const float4*)(g_H0 + (size_t)cj * FHID);
            float4 f0 = s[lane];
            float4 f1 = s[lane + 32];
            a0.x = fmaf(vj, f0.x, a0.x); a0.y = fmaf(vj, f0.y, a0.y);
            a0.z = fmaf(vj, f0.z, a0.z); a0.w = fmaf(vj, f0.w, a0.w);
            a1.x = fmaf(vj, f1.x, a1.x); a1.y = fmaf(vj, f1.y, a1.y);
            a1.z = fmaf(vj, f1.z, a1.z); a1.w = fmaf(vj, f1.w, a1.w);
        }
    }

    const float4* bb = (const float4*)b1;
    float4 t0 = bb[lane], t1 = bb[lane + 32];
    a0.x = fmaxf(a0.x + t0.x, 0.f); a0.y = fmaxf(a0.y + t0.y, 0.f);
    a0.z = fmaxf(a0.z + t0.z, 0.f); a0.w = fmaxf(a0.w + t0.w, 0.f);
    a1.x = fmaxf(a1.x + t1.x, 0.f); a1.y = fmaxf(a1.y + t1.y, 0.f);
    a1.z = fmaxf(a1.z + t1.z, 0.f); a1.w = fmaxf(a1.w + t1.w, 0.f);

    float4* d = (float4*)(g_H + (size_t)row * FHID);
    d[lane]      = a0;
    d[lane + 32] = a1;
}

// ---------------- GEMM2: g_P = g_H @ W2  (K=256, N=40) ------------------
#define W2STRIDE 260
__global__ __launch_bounds__(256) void gemm2_kernel(const float* __restrict__ W2) {
    __shared__ float shWT[NCLS * W2STRIDE];

    const int tid = threadIdx.x;
    for (int idx = tid; idx < FHID * NCLS; idx += 256) {
        int k = idx / NCLS, c = idx % NCLS;
        shWT[c * W2STRIDE + k] = W2[idx];
    }
    __syncthreads();

    const int rp = tid >> 3;
    const int c0 = (tid & 7) * 5;
    int r0 = blockIdx.x * 64 + rp * 2;
    int r1 = r0 + 1;
    bool v0 = r0 < NNODES, v1 = r1 < NNODES;
    int r0c = v0 ? r0 : NNODES - 1;
    int r1c = v1 ? r1 : NNODES - 1;

    const float4* h0 = (const float4*)(g_H + (size_t)r0c * FHID);
    const float4* h1 = (const float4*)(g_H + (size_t)r1c * FHID);

    float acc0[5] = {0.f, 0.f, 0.f, 0.f, 0.f};
    float acc1[5] = {0.f, 0.f, 0.f, 0.f, 0.f};

    #pragma unroll 4
    for (int kq = 0; kq < FHID / 4; kq++) {
        float4 ha = h0[kq];
        float4 hb = h1[kq];
        #pragma unroll
        for (int j = 0; j < 5; j++) {
            float4 w = *(const float4*)&shWT[(c0 + j) * W2STRIDE + kq * 4];
            acc0[j] = fmaf(ha.x, w.x, acc0[j]); acc0[j] = fmaf(ha.y, w.y, acc0[j]);
            acc0[j] = fmaf(ha.z, w.z, acc0[j]); acc0[j] = fmaf(ha.w, w.w, acc0[j]);
            acc1[j] = fmaf(hb.x, w.x, acc1[j]); acc1[j] = fmaf(hb.y, w.y, acc1[j]);
            acc1[j] = fmaf(hb.z, w.z, acc1[j]); acc1[j] = fmaf(hb.w, w.w, acc1[j]);
        }
    }

    if (v0) {
        float* p = g_P + (size_t)r0 * NCLS + c0;
        #pragma unroll
        for (int j = 0; j < 5; j++) p[j] = acc0[j];
    }
    if (v1) {
        float* p = g_P + (size_t)r1 * NCLS + c0;
        #pragma unroll
        for (int j = 0; j < 5; j++) p[j] = acc1[j];
    }
}

// ---------------- SpMM2 (CSR, warp/row) + bias + log_softmax ------------
__global__ __launch_bounds__(256) void spmm2_csr_kernel(const float* __restrict__ b2,
                                                        float* __restrict__ out) {
    int row  = blockIdx.x * 8 + (threadIdx.x >> 5);
    int lane = threadIdx.x & 31;
    int start = g_rowptr[row];
    int end   = g_rowptr[row + 1];

    float acc0 = 0.f, acc1 = 0.f;

    for (int e0 = start; e0 < end; e0 += 32) {
        int m = min(32, end - e0);
        int   c = 0;
        float v = 0.f;
        if (lane < m) { c = g_ccol[e0 + lane]; v = g_cval[e0 + lane]; }
        for (int j = 0; j < m; j++) {
            int   cj = __shfl_sync(0xFFFFFFFFu, c, j);
            float vj = __shfl_sync(0xFFFFFFFFu, v, j);
            const float* p = g_P + (size_t)cj * NCLS;
            float p0 = p[lane];
            float p1 = (lane < 8) ? p[32 + lane] : 0.f;
            acc0 = fmaf(vj, p0, acc0);
            acc1 = fmaf(vj, p1, acc1);
        }
    }

    float v0 = acc0 + b2[lane];
    float v1 = (lane < 8) ? (acc1 + b2[32 + lane]) : -INFINITY;

    float mx = fmaxf(v0, v1);
    #pragma unroll
    for (int off = 16; off > 0; off >>= 1)
        mx = fmaxf(mx, __shfl_xor_sync(0xFFFFFFFFu, mx, off));

    float s = expf(v0 - mx) + ((lane < 8) ? expf(v1 - mx) : 0.f);
    #pragma unroll
    for (int off = 16; off > 0; off >>= 1)
        s += __shfl_xor_sync(0xFFFFFFFFu, s, off);

    float ls = mx + logf(s);
    float* o = out + (size_t)row * NCLS;
    o[lane] = v0 - ls;
    if (lane < 8) o[32 + lane] = v1 - ls;
}

// ---------------- launch ----------------
extern "C" void kernel_launch(void* const* d_in, const int* in_sizes, int n_in,
                              void* d_out, int out_size) {
    const float* x    = (const float*)d_in[0];
    const void*  erow = d_in[1];
    const void*  ecol = d_in[2];
    const float* eval = (const float*)d_in[3];
    const float* W1   = (const float*)d_in[4];
    const float* b1   = (const float*)d_in[5];
    const float* W2   = (const float*)d_in[6];
    const float* b2   = (const float*)d_in[7];
    float* out = (float*)d_out;

    const int nchunks = (NNODES + 1023) / 1024;

    detect_kernel<<<1, 32>>>(erow);
    zero_deg_kernel<<<nchunks, 1024>>>();
    hist_kernel<<<NEDGES / 256, 256>>>(erow);
    scan_k1_kernel<<<nchunks, 1024>>>();
    scan_k2_kernel<<<1, 128>>>(nchunks);
    scan_k3_kernel<<<nchunks, 1024>>>();
    scatter_kernel<<<NEDGES / 256, 256>>>(erow, ecol, eval);

    {
        dim3 grid(FHID / 128, (NNODES + 127) / 128);  // (2, 782)
        gemm1_tc_kernel<<<grid, 256>>>(x, W1);
    }
    spmm1_csr_kernel<<<NNODES / 8, 256>>>(b1);
    gemm2_kernel<<<(NNODES + 63) / 64, 256>>>(W2);
    spmm2_csr_kernel<<<NNODES / 8, 256>>>(b2, out);
}